// round 2
// baseline (speedup 1.0000x reference)
#include <cuda_runtime.h>
#include <cstdint>

#define S_LEN 2048
#define HID 3072
#define NH 24
#define NKV 8
#define HD 128
#define ROT 96
#define OPSZ 5120            // NH*HD + 2*NKV*HD = 3072 + 2048
#define SCALING 0.08838834764831845f   // 128^-0.5

// Scratch (allocation-free rule: __device__ globals)
__device__ float g_qkv[(size_t)S_LEN * OPSZ];     // 42 MB
__device__ float g_ao [(size_t)S_LEN * HID];      // 25 MB

// ---------------------------------------------------------------------------
// Generic NT SGEMM: C[M,N] = alpha * A[M,K] * B[N,K]^T
// A row-major (K contiguous), B row-major (K contiguous).
// Block tile 128x128, K-tile 8, 256 threads, 8x8 per-thread microtile.
// All dims must be multiples of 128 (K multiple of 8) — true for this problem.
// ---------------------------------------------------------------------------
__global__ __launch_bounds__(256) void sgemm_nt(
    const float* __restrict__ A, int lda,
    const float* __restrict__ B, int ldb,
    float* __restrict__ C, int ldc,
    int K, float alpha)
{
    __shared__ float As[8][128];
    __shared__ float Bs[8][128];

    const int row0 = blockIdx.y * 128;
    const int col0 = blockIdx.x * 128;
    const int tid  = threadIdx.x;
    const int tx   = tid & 15;        // 0..15 -> 8 cols each
    const int ty   = tid >> 4;        // 0..15 -> 8 rows each
    const int ra   = tid >> 1;        // 0..127 (tile row for loads)
    const int ka   = (tid & 1) * 4;   // 0 or 4

    const float* Ap = A + (size_t)(row0 + ra) * lda + ka;
    const float* Bp = B + (size_t)(col0 + ra) * ldb + ka;

    float acc[8][8];
    #pragma unroll
    for (int i = 0; i < 8; i++)
        #pragma unroll
        for (int j = 0; j < 8; j++) acc[i][j] = 0.f;

    for (int k0 = 0; k0 < K; k0 += 8) {
        float4 a4 = *(const float4*)(Ap + k0);
        float4 b4 = *(const float4*)(Bp + k0);
        As[ka+0][ra] = a4.x; As[ka+1][ra] = a4.y;
        As[ka+2][ra] = a4.z; As[ka+3][ra] = a4.w;
        Bs[ka+0][ra] = b4.x; Bs[ka+1][ra] = b4.y;
        Bs[ka+2][ra] = b4.z; Bs[ka+3][ra] = b4.w;
        __syncthreads();

        #pragma unroll
        for (int kk = 0; kk < 8; kk++) {
            float a[8], b[8];
            #pragma unroll
            for (int i = 0; i < 8; i++) a[i] = As[kk][ty*8 + i];
            #pragma unroll
            for (int j = 0; j < 8; j++) b[j] = Bs[kk][tx*8 + j];
            #pragma unroll
            for (int i = 0; i < 8; i++)
                #pragma unroll
                for (int j = 0; j < 8; j++)
                    acc[i][j] = fmaf(a[i], b[j], acc[i][j]);
        }
        __syncthreads();
    }

    #pragma unroll
    for (int i = 0; i < 8; i++) {
        float* Cp = C + (size_t)(row0 + ty*8 + i) * ldc + col0 + tx*8;
        #pragma unroll
        for (int j = 0; j < 8; j++) Cp[j] = alpha * acc[i][j];
    }
}

// ---------------------------------------------------------------------------
// RoPE in-place on qkv: q heads (cols 0..3071) and k heads (cols 3072..4095).
// One thread per (s, head, pair i<48).
// ---------------------------------------------------------------------------
__global__ __launch_bounds__(256) void rope_kernel(
    float* __restrict__ qkv,
    const float* __restrict__ cosb,
    const float* __restrict__ sinb)
{
    int idx = blockIdx.x * blockDim.x + threadIdx.x;
    const int total = S_LEN * (NH + NKV) * 48;
    if (idx >= total) return;
    int i = idx % 48;
    int t = idx / 48;
    int h = t % (NH + NKV);
    int s = t / (NH + NKV);

    int col = (h < NH) ? h * HD : HID + (h - NH) * HD;
    float* p = qkv + (size_t)s * OPSZ + col;

    float c  = cosb[s * ROT + i];
    float sn = sinb[s * ROT + i];
    float x1 = p[i];
    float x2 = p[i + 48];
    p[i]      = x1 * c - x2 * sn;
    p[i + 48] = x2 * c + x1 * sn;
}

// ---------------------------------------------------------------------------
// Causal QK^T scores per head: C = Q_h K_{h/3}^T * SCALING (lower-tri blocks only)
// Upper-tri blocks are skipped entirely (softmax writes zeros there).
// ---------------------------------------------------------------------------
__global__ __launch_bounds__(256) void qk_scores(
    const float* __restrict__ qkv,
    float* __restrict__ attn)
{
    const int h    = blockIdx.z;
    const int row0 = blockIdx.y * 128;
    const int col0 = blockIdx.x * 128;
    if (col0 > row0) return;   // fully above diagonal

    const float* A = qkv + h * HD;                 // Q head, lda = OPSZ
    const float* B = qkv + HID + (h / 3) * HD;     // K head, ldb = OPSZ
    float* C = attn + (size_t)h * S_LEN * S_LEN;

    __shared__ float As[8][128];
    __shared__ float Bs[8][128];

    const int tid = threadIdx.x;
    const int tx  = tid & 15;
    const int ty  = tid >> 4;
    const int ra  = tid >> 1;
    const int ka  = (tid & 1) * 4;

    const float* Ap = A + (size_t)(row0 + ra) * OPSZ + ka;
    const float* Bp = B + (size_t)(col0 + ra) * OPSZ + ka;

    float acc[8][8];
    #pragma unroll
    for (int i = 0; i < 8; i++)
        #pragma unroll
        for (int j = 0; j < 8; j++) acc[i][j] = 0.f;

    #pragma unroll 1
    for (int k0 = 0; k0 < HD; k0 += 8) {
        float4 a4 = *(const float4*)(Ap + k0);
        float4 b4 = *(const float4*)(Bp + k0);
        As[ka+0][ra] = a4.x; As[ka+1][ra] = a4.y;
        As[ka+2][ra] = a4.z; As[ka+3][ra] = a4.w;
        Bs[ka+0][ra] = b4.x; Bs[ka+1][ra] = b4.y;
        Bs[ka+2][ra] = b4.z; Bs[ka+3][ra] = b4.w;
        __syncthreads();

        #pragma unroll
        for (int kk = 0; kk < 8; kk++) {
            float a[8], b[8];
            #pragma unroll
            for (int i = 0; i < 8; i++) a[i] = As[kk][ty*8 + i];
            #pragma unroll
            for (int j = 0; j < 8; j++) b[j] = Bs[kk][tx*8 + j];
            #pragma unroll
            for (int i = 0; i < 8; i++)
                #pragma unroll
                for (int j = 0; j < 8; j++)
                    acc[i][j] = fmaf(a[i], b[j], acc[i][j]);
        }
        __syncthreads();
    }

    #pragma unroll
    for (int i = 0; i < 8; i++) {
        float* Cp = C + (size_t)(row0 + ty*8 + i) * S_LEN + col0 + tx*8;
        #pragma unroll
        for (int j = 0; j < 8; j++) Cp[j] = SCALING * acc[i][j];
    }
}

// ---------------------------------------------------------------------------
// Causal softmax in place on the attn region. One block per (row, head).
// Valid columns: 0..row. Columns > row are written as exact 0.
// ---------------------------------------------------------------------------
__global__ __launch_bounds__(256) void softmax_causal(float* __restrict__ attn)
{
    const int r = blockIdx.x;
    const int h = blockIdx.y;
    float* row = attn + ((size_t)h * S_LEN + r) * S_LEN;
    const int nv  = r + 1;
    const int tid = threadIdx.x;

    float v[8];
    float mx = -1e30f;
    #pragma unroll
    for (int i = 0; i < 8; i++) {
        int c = tid + i * 256;
        v[i] = (c < nv) ? row[c] : -1e30f;
        mx = fmaxf(mx, v[i]);
    }

    __shared__ float red[256];
    red[tid] = mx;
    __syncthreads();
    #pragma unroll
    for (int s2 = 128; s2 > 0; s2 >>= 1) {
        if (tid < s2) red[tid] = fmaxf(red[tid], red[tid + s2]);
        __syncthreads();
    }
    mx = red[0];
    __syncthreads();

    float sum = 0.f;
    #pragma unroll
    for (int i = 0; i < 8; i++) {
        int c = tid + i * 256;
        v[i] = (c < nv) ? expf(v[i] - mx) : 0.f;
        sum += v[i];
    }
    red[tid] = sum;
    __syncthreads();
    #pragma unroll
    for (int s2 = 128; s2 > 0; s2 >>= 1) {
        if (tid < s2) red[tid] += red[tid + s2];
        __syncthreads();
    }
    const float inv = 1.f / red[0];

    #pragma unroll
    for (int i = 0; i < 8; i++) {
        int c = tid + i * 256;
        row[c] = v[i] * inv;
    }
}

// ---------------------------------------------------------------------------
// PV GEMM (NN) per head: ao[s, h*128 + d] = sum_k P[h,s,k] * V[h,k,d].
// K loop limited to row0+128 (P is exactly 0 above the diagonal).
// Block tile 128(M) x 128(N=full HD), K-tile 8.
// ---------------------------------------------------------------------------
__global__ __launch_bounds__(256) void pv_gemm(
    const float* __restrict__ attn,
    const float* __restrict__ qkv,
    float* __restrict__ ao)
{
    const int h    = blockIdx.z;
    const int row0 = blockIdx.y * 128;

    const float* A = attn + (size_t)h * S_LEN * S_LEN;            // P, lda = S
    const float* B = qkv + HID + NKV * HD + (h / 3) * HD;         // V, ldb = OPSZ
    float* C = ao + h * HD;                                       // ldc = HID

    __shared__ float As[8][128];
    __shared__ float Bs[8][128];

    const int tid = threadIdx.x;
    const int tx  = tid & 15;
    const int ty  = tid >> 4;
    const int ra  = tid >> 1;        // A load row (0..127)
    const int ka  = (tid & 1) * 4;   // A load k (0 or 4)
    const int kb  = tid >> 5;        // B load k-row (0..7)
    const int nb  = (tid & 31) * 4;  // B load col (0..124)

    const float* Ap = A + (size_t)(row0 + ra) * S_LEN + ka;

    float acc[8][8];
    #pragma unroll
    for (int i = 0; i < 8; i++)
        #pragma unroll
        for (int j = 0; j < 8; j++) acc[i][j] = 0.f;

    const int Keff = row0 + 128;
    for (int k0 = 0; k0 < Keff; k0 += 8) {
        float4 a4 = *(const float4*)(Ap + k0);
        float4 b4 = *(const float4*)(B + (size_t)(k0 + kb) * OPSZ + nb);
        As[ka+0][ra] = a4.x; As[ka+1][ra] = a4.y;
        As[ka+2][ra] = a4.z; As[ka+3][ra] = a4.w;
        *(float4*)(&Bs[kb][nb]) = b4;
        __syncthreads();

        #pragma unroll
        for (int kk = 0; kk < 8; kk++) {
            float a[8], b[8];
            #pragma unroll
            for (int i = 0; i < 8; i++) a[i] = As[kk][ty*8 + i];
            #pragma unroll
            for (int j = 0; j < 8; j++) b[j] = Bs[kk][tx*8 + j];
            #pragma unroll
            for (int i = 0; i < 8; i++)
                #pragma unroll
                for (int j = 0; j < 8; j++)
                    acc[i][j] = fmaf(a[i], b[j], acc[i][j]);
        }
        __syncthreads();
    }

    #pragma unroll
    for (int i = 0; i < 8; i++) {
        float* Cp = C + (size_t)(row0 + ty*8 + i) * HID + tx*8;
        #pragma unroll
        for (int j = 0; j < 8; j++) Cp[j] = acc[i][j];
    }
}

// ---------------------------------------------------------------------------
// Launch
// Inputs (metadata order): hidden_states, cos, sin, attention_mask, w_qkv, w_o
// Output: [out (1,2048,3072) fp32] ++ [attn_weights (1,24,2048,2048) fp32]
// ---------------------------------------------------------------------------
extern "C" void kernel_launch(void* const* d_in, const int* in_sizes, int n_in,
                              void* d_out, int out_size)
{
    const float* hidden = (const float*)d_in[0];
    const float* cosb   = (const float*)d_in[1];
    const float* sinb   = (const float*)d_in[2];
    const float* wqkv   = (const float*)d_in[4];
    const float* wo     = (const float*)d_in[5];

    float* out  = (float*)d_out;
    float* attn = out + (size_t)S_LEN * HID;   // attn_weights region of d_out

    float *qkv, *ao;
    cudaGetSymbolAddress((void**)&qkv, g_qkv);
    cudaGetSymbolAddress((void**)&ao,  g_ao);

    // 1. QKV = hidden @ w_qkv^T   (2048 x 5120, K=3072)
    sgemm_nt<<<dim3(OPSZ/128, S_LEN/128), 256>>>(hidden, HID, wqkv, HID,
                                                 qkv, OPSZ, HID, 1.0f);
    // 2. RoPE in place on q,k sections
    {
        int total = S_LEN * (NH + NKV) * 48;
        rope_kernel<<<(total + 255) / 256, 256>>>(qkv, cosb, sinb);
    }
    // 3. scores = Q K^T * scale  (lower-tri blocks only) -> attn region
    qk_scores<<<dim3(S_LEN/128, S_LEN/128, NH), 256>>>(qkv, attn);
    // 4. causal softmax in place (writes all columns incl. zeros)
    softmax_causal<<<dim3(S_LEN, NH), 256>>>(attn);
    // 5. attn_out = P @ V  (causal-limited K)
    pv_gemm<<<dim3(1, S_LEN/128, NH), 256>>>(attn, qkv, ao);
    // 6. out = attn_out @ w_o^T  (2048 x 3072, K=3072)
    sgemm_nt<<<dim3(HID/128, S_LEN/128), 256>>>(ao, HID, wo, HID,
                                                out, HID, HID, 1.0f);
}

// round 4
// speedup vs baseline: 2.7033x; 2.7033x over previous
#include <cuda_runtime.h>
#include <cuda_bf16.h>
#include <cstdint>

#define S_LEN 2048
#define HID 3072
#define NH 24
#define NKV 8
#define HD 128
#define ROT 96
#define OPSZ 5120
#define SCALING 0.08838834764831845f

// Scratch (__device__ globals; no runtime allocation allowed)
__device__ float g_qkv[(size_t)S_LEN * OPSZ];      // 42 MB
__device__ float g_ao [(size_t)S_LEN * HID];       // 25 MB
__device__ float g_vT [(size_t)NKV * HD * S_LEN];  // 8.4 MB  [kv][d][s]

// ---------------------------------------------------------------------------
// helpers
// ---------------------------------------------------------------------------
__device__ __forceinline__ uint32_t smem_u32(const void* p) {
    uint32_t a;
    asm("{ .reg .u64 t; cvta.to.shared.u64 t, %1; cvt.u32.u64 %0, t; }"
        : "=r"(a) : "l"(p));
    return a;
}

__device__ __forceinline__ void ldm4(uint32_t* r, uint32_t addr) {
    asm volatile("ldmatrix.sync.aligned.m8n8.x4.shared.b16 {%0,%1,%2,%3}, [%4];"
        : "=r"(r[0]), "=r"(r[1]), "=r"(r[2]), "=r"(r[3]) : "r"(addr));
}

__device__ __forceinline__ void mma16816(float* c, const uint32_t* a,
                                         const uint32_t* b) {
    asm volatile(
        "mma.sync.aligned.m16n8k16.row.col.f32.bf16.bf16.f32 "
        "{%0,%1,%2,%3}, {%4,%5,%6,%7}, {%8,%9}, {%0,%1,%2,%3};"
        : "+f"(c[0]), "+f"(c[1]), "+f"(c[2]), "+f"(c[3])
        : "r"(a[0]), "r"(a[1]), "r"(a[2]), "r"(a[3]), "r"(b[0]), "r"(b[1]));
}

__device__ __forceinline__ void sts128(uint32_t addr, uint4 v) {
    asm volatile("st.shared.v4.b32 [%0], {%1,%2,%3,%4};"
                 :: "r"(addr), "r"(v.x), "r"(v.y), "r"(v.z), "r"(v.w));
}

// pack two fp32 -> bf16x2 (lo half = a, hi half = b)
__device__ __forceinline__ uint32_t pk2(float a, float b) {
    uint32_t r;
    asm("cvt.rn.bf16x2.f32 %0, %1, %2;" : "=r"(r) : "f"(b), "f"(a));
    return r;
}

// 8 fp32 -> 8 bf16 hi + 8 bf16 lo (residual)
__device__ __forceinline__ void cvt8(float4 x, float4 y, uint4& hi, uint4& lo) {
    uint32_t p0 = pk2(x.x, x.y), p1 = pk2(x.z, x.w);
    uint32_t p2 = pk2(y.x, y.y), p3 = pk2(y.z, y.w);
    float l0 = x.x - __uint_as_float(p0 << 16);
    float l1 = x.y - __uint_as_float(p0 & 0xffff0000u);
    float l2 = x.z - __uint_as_float(p1 << 16);
    float l3 = x.w - __uint_as_float(p1 & 0xffff0000u);
    float l4 = y.x - __uint_as_float(p2 << 16);
    float l5 = y.y - __uint_as_float(p2 & 0xffff0000u);
    float l6 = y.z - __uint_as_float(p3 << 16);
    float l7 = y.w - __uint_as_float(p3 & 0xffff0000u);
    hi.x = p0; hi.y = p1; hi.z = p2; hi.w = p3;
    lo.x = pk2(l0, l1); lo.y = pk2(l2, l3);
    lo.z = pk2(l4, l5); lo.w = pk2(l6, l7);
}

// ---------------------------------------------------------------------------
// Generic NT GEMM on HMMA: C[M,N] = alpha * A[M,K] * B[N,K]^T  (fp32 I/O)
// 128x128 tile, 512 threads (16 warps, warp tile 32x32), K-chunk 32,
// compensated bf16 (3 HMMAs per k16). Double-buffered SMEM, 80B row pitch.
// flags: 1 = causal tile skip (col0 > row0), 2 = K limited to row0+128.
// ---------------------------------------------------------------------------
#define KC 32
#define TILE_B 10240u              // 128 rows * 80 B
#define BUF_B  (4u * TILE_B)       // Ah Al Bh Bl
#define GEMM_SMEM (2u * BUF_B)     // 81920 B

__global__ __launch_bounds__(512) void gemm_mma(
    const float* __restrict__ A, int lda, long long sAz,
    const float* __restrict__ B, int ldb, long long sBz, int kvdiv,
    float* __restrict__ C, int ldc, long long sCz,
    int K, float alpha, int flags)
{
    const int row0 = blockIdx.y << 7;
    const int col0 = blockIdx.x << 7;
    if ((flags & 1) && col0 > row0) return;
    const int z = blockIdx.z;
    A += (size_t)z * sAz;
    B += (size_t)(z / kvdiv) * sBz;
    C += (size_t)z * sCz;
    const int Keff = (flags & 2) ? ((K < row0 + 128) ? K : row0 + 128) : K;
    const int nCh  = Keff >> 5;

    extern __shared__ char smem[];
    const uint32_t base = smem_u32(smem);

    const int tid  = threadIdx.x;
    const int warp = tid >> 5;
    const int lane = tid & 31;
    const int wm   = warp >> 2;      // 0..3
    const int wn   = warp & 3;       // 0..3

    // producer mapping: row = tid>>2 (0..127), q = tid&3 (8 fp32 each)
    const int prow = tid >> 2;
    const int pq   = tid & 3;
    const float* aP = A + (size_t)(row0 + prow) * lda + pq * 8;
    const float* bP = B + (size_t)(col0 + prow) * ldb + pq * 8;
    const uint32_t pst = (uint32_t)prow * 80u + (uint32_t)pq * 16u;

    float acc[2][4][4];
#pragma unroll
    for (int mt = 0; mt < 2; mt++)
#pragma unroll
        for (int nt = 0; nt < 4; nt++)
#pragma unroll
            for (int r = 0; r < 4; r++) acc[mt][nt][r] = 0.f;

    // ldmatrix addresses (within a buffer)
    // A: row = wm*32 + mt*16 + (lane&15), slot = 2s + (lane>>4)
    const uint32_t aRow  = (uint32_t)(wm * 32 + (lane & 15));
    const uint32_t aSlot = (uint32_t)(lane >> 4);
    // B: n = wn*32 + g*16 + (lane&7) + ((lane>>4)<<3), slot = 2s + ((lane>>3)&1)
    const uint32_t bRow  = (uint32_t)(wn * 32 + (lane & 7) + ((lane >> 4) << 3));
    const uint32_t bSlot = (uint32_t)((lane >> 3) & 1);

    // preload chunk 0 into buffer 0
    {
        float4 a0 = *(const float4*)aP;
        float4 a1 = *(const float4*)(aP + 4);
        float4 b0 = *(const float4*)bP;
        float4 b1 = *(const float4*)(bP + 4);
        uint4 h, l;
        cvt8(a0, a1, h, l);
        sts128(base + pst, h);
        sts128(base + TILE_B + pst, l);
        cvt8(b0, b1, h, l);
        sts128(base + 2u * TILE_B + pst, h);
        sts128(base + 3u * TILE_B + pst, l);
    }
    __syncthreads();

    for (int i = 0; i < nCh; i++) {
        const uint32_t buf = base + (uint32_t)(i & 1) * BUF_B;
        const bool pf = (i + 1) < nCh;
        float4 pa0, pa1, pb0, pb1;
        if (pf) {
            const float* ap = aP + (size_t)(i + 1) * KC;
            const float* bp = bP + (size_t)(i + 1) * KC;
            pa0 = *(const float4*)ap; pa1 = *(const float4*)(ap + 4);
            pb0 = *(const float4*)bp; pb1 = *(const float4*)(bp + 4);
        }

#pragma unroll
        for (int s = 0; s < 2; s++) {
            uint32_t ah[2][4], al[2][4];
#pragma unroll
            for (int mt = 0; mt < 2; mt++) {
                uint32_t ad = buf + (aRow + (uint32_t)(mt * 16)) * 80u
                                  + (2u * s + aSlot) * 16u;
                ldm4(ah[mt], ad);
                ldm4(al[mt], ad + TILE_B);
            }
            uint32_t bh[4][2], bl[4][2];
#pragma unroll
            for (int g = 0; g < 2; g++) {
                uint32_t ad = buf + 2u * TILE_B
                                  + (bRow + (uint32_t)(g * 16)) * 80u
                                  + (2u * s + bSlot) * 16u;
                uint32_t t[4];
                ldm4(t, ad);
                bh[2*g][0] = t[0]; bh[2*g][1] = t[1];
                bh[2*g+1][0] = t[2]; bh[2*g+1][1] = t[3];
                ldm4(t, ad + TILE_B);
                bl[2*g][0] = t[0]; bl[2*g][1] = t[1];
                bl[2*g+1][0] = t[2]; bl[2*g+1][1] = t[3];
            }
#pragma unroll
            for (int mt = 0; mt < 2; mt++)
#pragma unroll
                for (int nt = 0; nt < 4; nt++) {
                    mma16816(acc[mt][nt], ah[mt], bh[nt]);
                    mma16816(acc[mt][nt], al[mt], bh[nt]);
                    mma16816(acc[mt][nt], ah[mt], bl[nt]);
                }
        }

        if (pf) {
            __syncthreads();
            const uint32_t nb = base + (uint32_t)((i + 1) & 1) * BUF_B;
            uint4 h, l;
            cvt8(pa0, pa1, h, l);
            sts128(nb + pst, h);
            sts128(nb + TILE_B + pst, l);
            cvt8(pb0, pb1, h, l);
            sts128(nb + 2u * TILE_B + pst, h);
            sts128(nb + 3u * TILE_B + pst, l);
            __syncthreads();
        }
    }

    // epilogue: c frag: rows lane/4 and lane/4+8, cols (lane%4)*2
#pragma unroll
    for (int mt = 0; mt < 2; mt++) {
        const int rbase = row0 + wm * 32 + mt * 16 + (lane >> 2);
#pragma unroll
        for (int nt = 0; nt < 4; nt++) {
            const int cbase = col0 + wn * 32 + nt * 8 + (lane & 3) * 2;
            float2 v0, v1;
            v0.x = alpha * acc[mt][nt][0];
            v0.y = alpha * acc[mt][nt][1];
            v1.x = alpha * acc[mt][nt][2];
            v1.y = alpha * acc[mt][nt][3];
            *(float2*)(C + (size_t)rbase * ldc + cbase)       = v0;
            *(float2*)(C + (size_t)(rbase + 8) * ldc + cbase) = v1;
        }
    }
}

// ---------------------------------------------------------------------------
// RoPE in-place on qkv (q: cols 0..3071, k: cols 3072..4095)
// ---------------------------------------------------------------------------
__global__ __launch_bounds__(256) void rope_kernel(
    float* __restrict__ qkv,
    const float* __restrict__ cosb,
    const float* __restrict__ sinb)
{
    int idx = blockIdx.x * blockDim.x + threadIdx.x;
    const int total = S_LEN * (NH + NKV) * 48;
    if (idx >= total) return;
    int i = idx % 48;
    int t = idx / 48;
    int h = t % (NH + NKV);
    int s = t / (NH + NKV);

    int col = (h < NH) ? h * HD : HID + (h - NH) * HD;
    float* p = qkv + (size_t)s * OPSZ + col;

    float c  = cosb[s * ROT + i];
    float sn = sinb[s * ROT + i];
    float x1 = p[i];
    float x2 = p[i + 48];
    p[i]      = x1 * c - x2 * sn;
    p[i + 48] = x2 * c + x1 * sn;
}

// ---------------------------------------------------------------------------
// V transpose: vT[kv*HD + d][s] = qkv[s][4096 + kv*HD + d]
// ---------------------------------------------------------------------------
__global__ __launch_bounds__(256) void transpose_v(
    const float* __restrict__ qkv, float* __restrict__ vT)
{
    int idx = blockIdx.x * 256 + threadIdx.x;     // s fastest
    if (idx >= NKV * HD * S_LEN) return;
    int s = idx & (S_LEN - 1);
    int t = idx >> 11;                            // kv*HD + d
    vT[(size_t)t * S_LEN + s] = qkv[(size_t)s * OPSZ + 4096 + t];
}

// ---------------------------------------------------------------------------
// Causal softmax in place. One block per (row, head). Cols > row set to 0.
// ---------------------------------------------------------------------------
__global__ __launch_bounds__(256) void softmax_causal(float* __restrict__ attn)
{
    const int r = blockIdx.x;
    const int h = blockIdx.y;
    float* row = attn + ((size_t)h * S_LEN + r) * S_LEN;
    const int nv  = r + 1;
    const int tid = threadIdx.x;

    float v[8];
    float mx = -1e30f;
#pragma unroll
    for (int i = 0; i < 8; i++) {
        int c = tid + i * 256;
        v[i] = (c < nv) ? row[c] : -1e30f;
        mx = fmaxf(mx, v[i]);
    }

    __shared__ float red[256];
    red[tid] = mx;
    __syncthreads();
#pragma unroll
    for (int s2 = 128; s2 > 0; s2 >>= 1) {
        if (tid < s2) red[tid] = fmaxf(red[tid], red[tid + s2]);
        __syncthreads();
    }
    mx = red[0];
    __syncthreads();

    float sum = 0.f;
#pragma unroll
    for (int i = 0; i < 8; i++) {
        int c = tid + i * 256;
        v[i] = (c < nv) ? expf(v[i] - mx) : 0.f;
        sum += v[i];
    }
    red[tid] = sum;
    __syncthreads();
#pragma unroll
    for (int s2 = 128; s2 > 0; s2 >>= 1) {
        if (tid < s2) red[tid] += red[tid + s2];
        __syncthreads();
    }
    const float inv = 1.f / red[0];

#pragma unroll
    for (int i = 0; i < 8; i++) {
        int c = tid + i * 256;
        row[c] = v[i] * inv;
    }
}

// ---------------------------------------------------------------------------
// Launch
// Inputs: hidden_states, cos, sin, attention_mask, w_qkv, w_o
// Output: [out (1,2048,3072)] ++ [attn_weights (1,24,2048,2048)]
// ---------------------------------------------------------------------------
extern "C" void kernel_launch(void* const* d_in, const int* in_sizes, int n_in,
                              void* d_out, int out_size)
{
    const float* hidden = (const float*)d_in[0];
    const float* cosb   = (const float*)d_in[1];
    const float* sinb   = (const float*)d_in[2];
    const float* wqkv   = (const float*)d_in[4];
    const float* wo     = (const float*)d_in[5];

    float* out  = (float*)d_out;
    float* attn = out + (size_t)S_LEN * HID;

    float *qkv, *ao, *vT;
    cudaGetSymbolAddress((void**)&qkv, g_qkv);
    cudaGetSymbolAddress((void**)&ao,  g_ao);
    cudaGetSymbolAddress((void**)&vT,  g_vT);

    cudaFuncSetAttribute(gemm_mma, cudaFuncAttributeMaxDynamicSharedMemorySize,
                         GEMM_SMEM);

    // 1. qkv = hidden @ w_qkv^T   (2048 x 5120, K=3072)
    gemm_mma<<<dim3(OPSZ / 128, S_LEN / 128, 1), 512, GEMM_SMEM>>>(
        hidden, HID, 0, wqkv, HID, 0, 1, qkv, OPSZ, 0, HID, 1.0f, 0);

    // 2. RoPE in place
    {
        int total = S_LEN * (NH + NKV) * 48;
        rope_kernel<<<(total + 255) / 256, 256>>>(qkv, cosb, sinb);
    }

    // 3. vT = transpose(v)
    transpose_v<<<(NKV * HD * S_LEN) / 256, 256>>>(qkv, vT);

    // 4. scores = Q K^T * scale (causal tiles only) -> attn region
    gemm_mma<<<dim3(S_LEN / 128, S_LEN / 128, NH), 512, GEMM_SMEM>>>(
        qkv, OPSZ, HD,
        qkv + HID, OPSZ, HD, 3,
        attn, S_LEN, (long long)S_LEN * S_LEN,
        HD, SCALING, 1);

    // 5. causal softmax in place
    softmax_causal<<<dim3(S_LEN, NH), 256>>>(attn);

    // 6. ao = P @ V   (K limited to row0+128)
    gemm_mma<<<dim3(1, S_LEN / 128, NH), 512, GEMM_SMEM>>>(
        attn, S_LEN, (long long)S_LEN * S_LEN,
        vT, S_LEN, (long long)HD * S_LEN, 3,
        ao, HID, HD,
        S_LEN, 1.0f, 2);

    // 7. out = ao @ w_o^T   (2048 x 3072, K=3072)
    gemm_mma<<<dim3(HID / 128, S_LEN / 128, 1), 512, GEMM_SMEM>>>(
        ao, HID, 0, wo, HID, 0, 1, out, HID, 0, HID, 1.0f, 0);
}

// round 5
// speedup vs baseline: 2.7693x; 1.0244x over previous
#include <cuda_runtime.h>
#include <cuda_bf16.h>
#include <cstdint>

#define S_LEN 2048
#define HID 3072
#define NH 24
#define NKV 8
#define HD 128
#define OPSZ 5120
#define QK_COLS 4096
#define SCALING 0.08838834764831845f

// ---------------------------------------------------------------------------
// Scratch (__device__ globals; runtime allocation forbidden)
// ---------------------------------------------------------------------------
__device__ float g_qkv[(size_t)S_LEN * OPSZ];                                  // 42 MB
__device__ __nv_bfloat16 g_hidh [(size_t)S_LEN * HID],  g_hidl [(size_t)S_LEN * HID];
__device__ __nv_bfloat16 g_wqkvh[(size_t)OPSZ * HID],   g_wqkvl[(size_t)OPSZ * HID];
__device__ __nv_bfloat16 g_woh  [(size_t)HID * HID],    g_wol  [(size_t)HID * HID];
__device__ __nv_bfloat16 g_qkh  [(size_t)S_LEN * QK_COLS], g_qkl[(size_t)S_LEN * QK_COLS];
__device__ __nv_bfloat16 g_vTh  [(size_t)NKV * HD * S_LEN], g_vTl[(size_t)NKV * HD * S_LEN];
__device__ __nv_bfloat16 g_Ph   [(size_t)NH * S_LEN * S_LEN];                  // 201 MB
__device__ __nv_bfloat16 g_Pl   [(size_t)NH * S_LEN * S_LEN];                  // 201 MB
__device__ __nv_bfloat16 g_aoh  [(size_t)S_LEN * HID],  g_aol [(size_t)S_LEN * HID];

// ---------------------------------------------------------------------------
// helpers
// ---------------------------------------------------------------------------
__device__ __forceinline__ uint32_t smem_u32(const void* p) {
    uint32_t a;
    asm("{ .reg .u64 t; cvta.to.shared.u64 t, %1; cvt.u32.u64 %0, t; }"
        : "=r"(a) : "l"(p));
    return a;
}
__device__ __forceinline__ void ldm4(uint32_t* r, uint32_t addr) {
    asm volatile("ldmatrix.sync.aligned.m8n8.x4.shared.b16 {%0,%1,%2,%3}, [%4];"
        : "=r"(r[0]), "=r"(r[1]), "=r"(r[2]), "=r"(r[3]) : "r"(addr));
}
__device__ __forceinline__ void mma16816(float* c, const uint32_t* a,
                                         const uint32_t* b) {
    asm volatile(
        "mma.sync.aligned.m16n8k16.row.col.f32.bf16.bf16.f32 "
        "{%0,%1,%2,%3}, {%4,%5,%6,%7}, {%8,%9}, {%0,%1,%2,%3};"
        : "+f"(c[0]), "+f"(c[1]), "+f"(c[2]), "+f"(c[3])
        : "r"(a[0]), "r"(a[1]), "r"(a[2]), "r"(a[3]), "r"(b[0]), "r"(b[1]));
}
// pack two fp32 -> bf16x2 (lo half = a, hi half = b), round-to-nearest
__device__ __forceinline__ uint32_t pk2(float a, float b) {
    uint32_t r;
    asm("cvt.rn.bf16x2.f32 %0, %1, %2;" : "=r"(r) : "f"(b), "f"(a));
    return r;
}
#define CP16(dst, src) \
    asm volatile("cp.async.cg.shared.global [%0], [%1], 16;" \
                 :: "r"(dst), "l"(src) : "memory")
#define CP_COMMIT() asm volatile("cp.async.commit_group;" ::: "memory")
#define CP_WAIT2()  asm volatile("cp.async.wait_group 2;" ::: "memory")

// ---------------------------------------------------------------------------
// fp32 -> (bf16 hi, bf16 lo) elementwise split, 4 elems/thread
// ---------------------------------------------------------------------------
__global__ __launch_bounds__(256) void conv_split(
    const float* __restrict__ src, __nv_bfloat16* __restrict__ h,
    __nv_bfloat16* __restrict__ l, int n4)
{
    int i = blockIdx.x * 256 + threadIdx.x;
    if (i >= n4) return;
    float4 x = ((const float4*)src)[i];
    uint32_t p0 = pk2(x.x, x.y), p1 = pk2(x.z, x.w);
    float l0 = x.x - __uint_as_float(p0 << 16);
    float l1 = x.y - __uint_as_float(p0 & 0xffff0000u);
    float l2 = x.z - __uint_as_float(p1 << 16);
    float l3 = x.w - __uint_as_float(p1 & 0xffff0000u);
    uint2 hh; hh.x = p0; hh.y = p1;
    uint2 ll; ll.x = pk2(l0, l1); ll.y = pk2(l2, l3);
    ((uint2*)h)[i] = hh;
    ((uint2*)l)[i] = ll;
}

// ---------------------------------------------------------------------------
// Fused RoPE + split on Q/K columns (0..4095) of qkv. 4 elems/thread.
// ---------------------------------------------------------------------------
__global__ __launch_bounds__(256) void rope_split(
    const float* __restrict__ qkv, const float* __restrict__ cosb,
    const float* __restrict__ sinb,
    __nv_bfloat16* __restrict__ qh, __nv_bfloat16* __restrict__ ql)
{
    int idx = blockIdx.x * 256 + threadIdx.x;   // S_LEN * 1024
    int s = idx >> 10;
    int c = (idx & 1023) * 4;
    int d = c & 127;
    const float* row = qkv + (size_t)s * OPSZ;
    float4 x = *(const float4*)(row + c);
    if (d < 96) {
        float4 cc = *(const float4*)(cosb + s * 96 + d);
        float4 ss = *(const float4*)(sinb + s * 96 + d);
        if (d < 48) {
            float4 p = *(const float4*)(row + c + 48);
            x.x = x.x * cc.x - p.x * ss.x;
            x.y = x.y * cc.y - p.y * ss.y;
            x.z = x.z * cc.z - p.z * ss.z;
            x.w = x.w * cc.w - p.w * ss.w;
        } else {
            float4 p = *(const float4*)(row + c - 48);
            x.x = x.x * cc.x + p.x * ss.x;
            x.y = x.y * cc.y + p.y * ss.y;
            x.z = x.z * cc.z + p.z * ss.z;
            x.w = x.w * cc.w + p.w * ss.w;
        }
    }
    uint32_t p0 = pk2(x.x, x.y), p1 = pk2(x.z, x.w);
    float l0 = x.x - __uint_as_float(p0 << 16);
    float l1 = x.y - __uint_as_float(p0 & 0xffff0000u);
    float l2 = x.z - __uint_as_float(p1 << 16);
    float l3 = x.w - __uint_as_float(p1 & 0xffff0000u);
    uint2 hh; hh.x = p0; hh.y = p1;
    uint2 ll; ll.x = pk2(l0, l1); ll.y = pk2(l2, l3);
    size_t o = ((size_t)s * QK_COLS + c) >> 2;
    ((uint2*)qh)[o] = hh;
    ((uint2*)ql)[o] = ll;
}

// ---------------------------------------------------------------------------
// V transpose + split: vT[kv*HD+d][s] = qkv[s][4096+kv*HD+d], SMEM-tiled.
// ---------------------------------------------------------------------------
__global__ __launch_bounds__(256) void vsplit_T(
    const float* __restrict__ qkv,
    __nv_bfloat16* __restrict__ vh, __nv_bfloat16* __restrict__ vl)
{
    __shared__ float tile[32][33];
    const int t0 = blockIdx.x * 32;
    const int s0 = blockIdx.y * 32;
    const int tx = threadIdx.x, ty = threadIdx.y;   // (32, 8)
#pragma unroll
    for (int j = 0; j < 4; j++)
        tile[ty + 8 * j][tx] =
            qkv[(size_t)(s0 + ty + 8 * j) * OPSZ + 4096 + t0 + tx];
    __syncthreads();
#pragma unroll
    for (int j = 0; j < 4; j++) {
        float v = tile[tx][ty + 8 * j];
        __nv_bfloat16 hb = __float2bfloat16(v);
        size_t o = (size_t)(t0 + ty + 8 * j) * S_LEN + s0 + tx;
        vh[o] = hb;
        vl[o] = __float2bfloat16(v - __bfloat162float(hb));
    }
}

// ---------------------------------------------------------------------------
// Generic NT GEMM, bf16 hi/lo operands, compensated (3 HMMA per k16).
// C[M,N] = alpha * (Ah+Al)[M,K] * (Bh+Bl)[N,K]^T  (dropping AlBl term)
// 128x128 tile, 512 threads (16 warps, warp tile 32x32), KC=32,
// 4-stage cp.async pipeline, 80B SMEM row pitch (conflict-free ldmatrix).
// flags: 1 = causal tile skip, 2 = K limited to row0+128, 4 = split output.
// ---------------------------------------------------------------------------
#define KC 32
#define TILE_B  10240u             // 128 rows * 80 B
#define STAGE_B 40960u             // Ah Al Bh Bl
#define NSTAGE  4
#define GEMM_SMEM (NSTAGE * STAGE_B)   // 163840

__global__ __launch_bounds__(512) void gemm_bf16(
    const __nv_bfloat16* __restrict__ Ah, const __nv_bfloat16* __restrict__ Al,
    int lda, long long sAz,
    const __nv_bfloat16* __restrict__ Bh, const __nv_bfloat16* __restrict__ Bl,
    int ldb, long long sBz, int kvdiv,
    float* __restrict__ Cf, __nv_bfloat16* __restrict__ Ch,
    __nv_bfloat16* __restrict__ Cl, int ldc, long long sCz,
    int K, float alpha, int flags)
{
    const int row0 = blockIdx.y << 7;
    const int col0 = blockIdx.x << 7;
    if ((flags & 1) && col0 > row0) return;
    const int z = blockIdx.z;
    const size_t za = (size_t)z * sAz;
    const size_t zb = (size_t)(z / kvdiv) * sBz;
    const size_t zc = (size_t)z * sCz;
    Ah += za; Al += za; Bh += zb; Bl += zb;
    const int Keff = (flags & 2) ? ((K < row0 + 128) ? K : row0 + 128) : K;
    const int nCh  = Keff >> 5;

    extern __shared__ char smem[];
    const uint32_t base = smem_u32(smem);

    const int tid  = threadIdx.x;
    const int warp = tid >> 5;
    const int lane = tid & 31;
    const int wm   = warp >> 2;
    const int wn   = warp & 3;

    // producer mapping: row = tid>>2 (0..127), 16B chunk = tid&3
    const int prow = tid >> 2;
    const int pq   = tid & 3;
    const uint32_t pst = (uint32_t)prow * 80u + (uint32_t)pq * 16u;
    const __nv_bfloat16* pAh = Ah + (size_t)(row0 + prow) * lda + pq * 8;
    const __nv_bfloat16* pAl = Al + (size_t)(row0 + prow) * lda + pq * 8;
    const __nv_bfloat16* pBh = Bh + (size_t)(col0 + prow) * ldb + pq * 8;
    const __nv_bfloat16* pBl = Bl + (size_t)(col0 + prow) * ldb + pq * 8;

    // prologue: stages 0..2 (nCh >= 4 for every launch in this problem)
#pragma unroll
    for (int s = 0; s < NSTAGE - 1; s++) {
        const int kO = s * KC;
        const uint32_t dst = base + (uint32_t)s * STAGE_B + pst;
        CP16(dst,              pAh + kO);
        CP16(dst + TILE_B,     pAl + kO);
        CP16(dst + 2 * TILE_B, pBh + kO);
        CP16(dst + 3 * TILE_B, pBl + kO);
        CP_COMMIT();
    }

    float acc[2][4][4];
#pragma unroll
    for (int mt = 0; mt < 2; mt++)
#pragma unroll
        for (int nt = 0; nt < 4; nt++)
#pragma unroll
            for (int r = 0; r < 4; r++) acc[mt][nt][r] = 0.f;

    const uint32_t aRow  = (uint32_t)(wm * 32 + (lane & 15));
    const uint32_t aSlot = (uint32_t)(lane >> 4);
    const uint32_t bRow  = (uint32_t)(wn * 32 + (lane & 7) + ((lane >> 4) << 3));
    const uint32_t bSlot = (uint32_t)((lane >> 3) & 1);

    for (int i = 0; i < nCh; i++) {
        CP_WAIT2();                 // stage i landed
        __syncthreads();            // all warps done with stage (i-1)%4
        if (i + NSTAGE - 1 < nCh) {
            const int kO = (i + NSTAGE - 1) * KC;
            const uint32_t dst =
                base + (uint32_t)((i + NSTAGE - 1) & (NSTAGE - 1)) * STAGE_B + pst;
            CP16(dst,              pAh + kO);
            CP16(dst + TILE_B,     pAl + kO);
            CP16(dst + 2 * TILE_B, pBh + kO);
            CP16(dst + 3 * TILE_B, pBl + kO);
        }
        CP_COMMIT();

        const uint32_t buf = base + (uint32_t)(i & (NSTAGE - 1)) * STAGE_B;
#pragma unroll
        for (int s = 0; s < 2; s++) {
            uint32_t ah[2][4], al[2][4];
#pragma unroll
            for (int mt = 0; mt < 2; mt++) {
                uint32_t ad = buf + (aRow + (uint32_t)(mt * 16)) * 80u
                                  + (2u * s + aSlot) * 16u;
                ldm4(ah[mt], ad);
                ldm4(al[mt], ad + TILE_B);
            }
            uint32_t bh[4][2], bl[4][2];
#pragma unroll
            for (int g = 0; g < 2; g++) {
                uint32_t ad = buf + 2u * TILE_B
                                  + (bRow + (uint32_t)(g * 16)) * 80u
                                  + (2u * s + bSlot) * 16u;
                uint32_t t[4];
                ldm4(t, ad);
                bh[2*g][0] = t[0]; bh[2*g][1] = t[1];
                bh[2*g+1][0] = t[2]; bh[2*g+1][1] = t[3];
                ldm4(t, ad + TILE_B);
                bl[2*g][0] = t[0]; bl[2*g][1] = t[1];
                bl[2*g+1][0] = t[2]; bl[2*g+1][1] = t[3];
            }
#pragma unroll
            for (int mt = 0; mt < 2; mt++)
#pragma unroll
                for (int nt = 0; nt < 4; nt++) {
                    mma16816(acc[mt][nt], ah[mt], bh[nt]);
                    mma16816(acc[mt][nt], al[mt], bh[nt]);
                    mma16816(acc[mt][nt], ah[mt], bl[nt]);
                }
        }
    }

    // epilogue
#pragma unroll
    for (int mt = 0; mt < 2; mt++) {
        const int rbase = row0 + wm * 32 + mt * 16 + (lane >> 2);
#pragma unroll
        for (int nt = 0; nt < 4; nt++) {
            const int cbase = col0 + wn * 32 + nt * 8 + (lane & 3) * 2;
            float v00 = alpha * acc[mt][nt][0];
            float v01 = alpha * acc[mt][nt][1];
            float v10 = alpha * acc[mt][nt][2];
            float v11 = alpha * acc[mt][nt][3];
            if (flags & 4) {
                uint32_t h0 = pk2(v00, v01);
                uint32_t l0 = pk2(v00 - __uint_as_float(h0 << 16),
                                  v01 - __uint_as_float(h0 & 0xffff0000u));
                uint32_t h1 = pk2(v10, v11);
                uint32_t l1 = pk2(v10 - __uint_as_float(h1 << 16),
                                  v11 - __uint_as_float(h1 & 0xffff0000u));
                *(uint32_t*)(Ch + zc + (size_t)rbase * ldc + cbase)       = h0;
                *(uint32_t*)(Cl + zc + (size_t)rbase * ldc + cbase)       = l0;
                *(uint32_t*)(Ch + zc + (size_t)(rbase + 8) * ldc + cbase) = h1;
                *(uint32_t*)(Cl + zc + (size_t)(rbase + 8) * ldc + cbase) = l1;
            } else {
                float2 v0; v0.x = v00; v0.y = v01;
                float2 v1; v1.x = v10; v1.y = v11;
                *(float2*)(Cf + zc + (size_t)rbase * ldc + cbase)       = v0;
                *(float2*)(Cf + zc + (size_t)(rbase + 8) * ldc + cbase) = v1;
            }
        }
    }
}

// ---------------------------------------------------------------------------
// Causal softmax in place; also emits bf16 hi/lo split of P for the PV GEMM.
// One block per (row, head). Cols > row set to exact 0.
// ---------------------------------------------------------------------------
__global__ __launch_bounds__(256) void softmax_causal(
    float* __restrict__ attn,
    __nv_bfloat16* __restrict__ Ph, __nv_bfloat16* __restrict__ Pl)
{
    const int r = blockIdx.x;
    const int h = blockIdx.y;
    const size_t ro = ((size_t)h * S_LEN + r) * S_LEN;
    float* row = attn + ro;
    const int nv  = r + 1;
    const int tid = threadIdx.x;

    float v[8];
    float mx = -1e30f;
#pragma unroll
    for (int i = 0; i < 8; i++) {
        int c = tid + i * 256;
        v[i] = (c < nv) ? row[c] : -1e30f;
        mx = fmaxf(mx, v[i]);
    }

    __shared__ float red[256];
    red[tid] = mx;
    __syncthreads();
#pragma unroll
    for (int s2 = 128; s2 > 0; s2 >>= 1) {
        if (tid < s2) red[tid] = fmaxf(red[tid], red[tid + s2]);
        __syncthreads();
    }
    mx = red[0];
    __syncthreads();

    float sum = 0.f;
#pragma unroll
    for (int i = 0; i < 8; i++) {
        int c = tid + i * 256;
        v[i] = (c < nv) ? expf(v[i] - mx) : 0.f;
        sum += v[i];
    }
    red[tid] = sum;
    __syncthreads();
#pragma unroll
    for (int s2 = 128; s2 > 0; s2 >>= 1) {
        if (tid < s2) red[tid] += red[tid + s2];
        __syncthreads();
    }
    const float inv = 1.f / red[0];

#pragma unroll
    for (int i = 0; i < 8; i++) {
        int c = tid + i * 256;
        float val = v[i] * inv;
        row[c] = val;
        __nv_bfloat16 hb = __float2bfloat16(val);
        Ph[ro + c] = hb;
        Pl[ro + c] = __float2bfloat16(val - __bfloat162float(hb));
    }
}

// ---------------------------------------------------------------------------
// Launch
// Inputs: hidden_states, cos, sin, attention_mask, w_qkv, w_o
// Output: [out (1,2048,3072)] ++ [attn_weights (1,24,2048,2048)]
// ---------------------------------------------------------------------------
extern "C" void kernel_launch(void* const* d_in, const int* in_sizes, int n_in,
                              void* d_out, int out_size)
{
    const float* hidden = (const float*)d_in[0];
    const float* cosb   = (const float*)d_in[1];
    const float* sinb   = (const float*)d_in[2];
    const float* wqkv   = (const float*)d_in[4];
    const float* wo     = (const float*)d_in[5];

    float* out  = (float*)d_out;
    float* attn = out + (size_t)S_LEN * HID;

    float* qkv;
    __nv_bfloat16 *hidh, *hidl, *wqkvh, *wqkvl, *woh, *wol;
    __nv_bfloat16 *qkh, *qkl, *vTh, *vTl, *Ph, *Pl, *aoh, *aol;
    cudaGetSymbolAddress((void**)&qkv,   g_qkv);
    cudaGetSymbolAddress((void**)&hidh,  g_hidh);
    cudaGetSymbolAddress((void**)&hidl,  g_hidl);
    cudaGetSymbolAddress((void**)&wqkvh, g_wqkvh);
    cudaGetSymbolAddress((void**)&wqkvl, g_wqkvl);
    cudaGetSymbolAddress((void**)&woh,   g_woh);
    cudaGetSymbolAddress((void**)&wol,   g_wol);
    cudaGetSymbolAddress((void**)&qkh,   g_qkh);
    cudaGetSymbolAddress((void**)&qkl,   g_qkl);
    cudaGetSymbolAddress((void**)&vTh,   g_vTh);
    cudaGetSymbolAddress((void**)&vTl,   g_vTl);
    cudaGetSymbolAddress((void**)&Ph,    g_Ph);
    cudaGetSymbolAddress((void**)&Pl,    g_Pl);
    cudaGetSymbolAddress((void**)&aoh,   g_aoh);
    cudaGetSymbolAddress((void**)&aol,   g_aol);

    cudaFuncSetAttribute(gemm_bf16, cudaFuncAttributeMaxDynamicSharedMemorySize,
                         GEMM_SMEM);

    // 0. operand splits
    conv_split<<<(S_LEN * HID / 4 + 255) / 256, 256>>>(hidden, hidh, hidl,
                                                       S_LEN * HID / 4);
    conv_split<<<(OPSZ * HID / 4 + 255) / 256, 256>>>(wqkv, wqkvh, wqkvl,
                                                      OPSZ * HID / 4);
    conv_split<<<(HID * HID / 4 + 255) / 256, 256>>>(wo, woh, wol,
                                                     HID * HID / 4);

    // 1. qkv = hidden @ w_qkv^T   (2048 x 5120, K=3072), fp32 out
    gemm_bf16<<<dim3(OPSZ / 128, S_LEN / 128, 1), 512, GEMM_SMEM>>>(
        hidh, hidl, HID, 0, wqkvh, wqkvl, HID, 0, 1,
        qkv, nullptr, nullptr, OPSZ, 0, HID, 1.0f, 0);

    // 2. RoPE + split Q/K;  3. transpose + split V
    rope_split<<<S_LEN * 1024 / 256, 256>>>(qkv, cosb, sinb, qkh, qkl);
    vsplit_T<<<dim3((NKV * HD) / 32, S_LEN / 32), dim3(32, 8)>>>(qkv, vTh, vTl);

    // 4. scores = Q K^T * scale (causal tiles only) -> attn fp32
    gemm_bf16<<<dim3(S_LEN / 128, S_LEN / 128, NH), 512, GEMM_SMEM>>>(
        qkh, qkl, QK_COLS, HD,
        qkh + HID, qkl + HID, QK_COLS, HD, 3,
        attn, nullptr, nullptr, S_LEN, (long long)S_LEN * S_LEN,
        HD, SCALING, 1);

    // 5. softmax in place + P hi/lo emit
    softmax_causal<<<dim3(S_LEN, NH), 256>>>(attn, Ph, Pl);

    // 6. ao(hi/lo) = P @ V   (K limited to row0+128)
    gemm_bf16<<<dim3(1, S_LEN / 128, NH), 512, GEMM_SMEM>>>(
        Ph, Pl, S_LEN, (long long)S_LEN * S_LEN,
        vTh, vTl, S_LEN, (long long)HD * S_LEN, 3,
        nullptr, aoh, aol, HID, HD,
        S_LEN, 1.0f, 2 | 4);

    // 7. out = ao @ w_o^T   (2048 x 3072, K=3072), fp32 out
    gemm_bf16<<<dim3(HID / 128, S_LEN / 128, 1), 512, GEMM_SMEM>>>(
        aoh, aol, HID, 0, woh, wol, HID, 0, 1,
        out, nullptr, nullptr, HID, 0, HID, 1.0f, 0);
}